// round 10
// baseline (speedup 1.0000x reference)
#include <cuda_runtime.h>
#include <cuda_bf16.h>
#include <cstdint>
#include <cstddef>

#define NMAX 100000
#define EMAX 1700000
#define FD 128

typedef unsigned int uint;

// Scratch — static __device__ globals, referenced only from device code.
__device__ __align__(16) float g_dinv[NMAX];
__device__ __align__(16) float g_h[(size_t)NMAX * FD];   // GEMM output
__device__ __align__(16) float g_a[(size_t)NMAX * FD];   // layer-1 activation
__device__ int   g_is64;
// CSR
__device__ int   g_cnt[NMAX];
__device__ int   g_fill[NMAX];
__device__ int   g_rowptr[NMAX + 1];
__device__ int   g_bsum[128];
__device__ int   g_boff[128];
__device__ int   g_ccol[EMAX];
__device__ float g_cnorm[EMAX];
// bf16-split W images, transposed [N][K], packed 2 bf16 per uint (k-pairs)
__device__ __align__(16) uint g_wthi1[8192], g_wtlo1[8192];
__device__ __align__(16) uint g_wthi2[8192], g_wtlo2[8192];

// ---------------- helpers ----------------
__device__ __forceinline__ uint32_t smem_u32(const void* p) {
    uint32_t a;
    asm("{ .reg .u64 t; cvta.to.shared.u64 t, %1; cvt.u32.u64 %0, t; }"
        : "=r"(a) : "l"(p));
    return a;
}

__device__ __forceinline__ void ldsm_x4(uint* r, uint32_t addr) {
    asm volatile("ldmatrix.sync.aligned.m8n8.x4.shared.b16 {%0,%1,%2,%3}, [%4];"
                 : "=r"(r[0]), "=r"(r[1]), "=r"(r[2]), "=r"(r[3]) : "r"(addr));
}

__device__ __forceinline__ void mma_bf16(float* c, const uint* a, uint b0, uint b1) {
    asm volatile("mma.sync.aligned.m16n8k16.row.col.f32.bf16.bf16.f32 "
                 "{%0,%1,%2,%3}, {%4,%5,%6,%7}, {%8,%9}, {%0,%1,%2,%3};"
                 : "+f"(c[0]), "+f"(c[1]), "+f"(c[2]), "+f"(c[3])
                 : "r"(a[0]), "r"(a[1]), "r"(a[2]), "r"(a[3]), "r"(b0), "r"(b1));
}

__device__ __forceinline__ void split_bf16(float a, unsigned short& hi, unsigned short& lo) {
    __nv_bfloat16 h = __float2bfloat16(a);
    float hf = __bfloat162float(h);
    __nv_bfloat16 l = __float2bfloat16(a - hf);
    hi = __bfloat16_as_ushort(h);
    lo = __bfloat16_as_ushort(l);
}

// ---------------- zero + dtype detection ----------------
__global__ void zero_detect_kernel(const int* __restrict__ ei32, int E, int n) {
    int i = blockIdx.x * blockDim.x + threadIdx.x;
    if (i < n) { g_dinv[i] = 1.0f; g_cnt[i] = 0; g_fill[i] = 0; }
    if (blockIdx.x == 0) {
        __shared__ int snz;
        if (threadIdx.x == 0) snz = 0;
        __syncthreads();
        int cnt = E < 4096 ? E : 4096, nz = 0;
        for (int j = threadIdx.x; j < cnt; j += blockDim.x) nz |= ei32[2 * j + 1];
        if (nz) atomicOr(&snz, 1);
        __syncthreads();
        if (threadIdx.x == 0) g_is64 = (snz == 0) ? 1 : 0;
    }
}

__device__ __forceinline__ int edge_row(const int* ei32, int E, int e) {
    return g_is64 ? ei32[2 * (size_t)e] : ei32[e];
}
__device__ __forceinline__ int edge_col(const int* ei32, int E, int e) {
    return g_is64 ? ei32[2 * (size_t)E + 2 * (size_t)e] : ei32[(size_t)E + e];
}

// ---------------- W split: W[K,N] fp32 -> Wt hi/lo bf16 [N][K] ------------
__global__ void wconv_kernel(const float* __restrict__ W,
                             uint* __restrict__ whi, uint* __restrict__ wlo) {
    int idx = blockIdx.x * 256 + threadIdx.x;     // 8192 k-pairs
    if (idx >= 8192) return;
    int nrow = idx >> 6;
    int k    = (idx & 63) << 1;
    unsigned short h0, l0, h1, l1;
    split_bf16(W[(size_t)k * FD + nrow], h0, l0);
    split_bf16(W[(size_t)(k + 1) * FD + nrow], h1, l1);
    whi[idx] = ((uint)h1 << 16) | h0;
    wlo[idx] = ((uint)l1 << 16) | l0;
}

// ---------------- degree + CSR build ----------------
__global__ void deg_count_kernel(const int* __restrict__ ei32,
                                 const float* __restrict__ w, int E) {
    int e = blockIdx.x * blockDim.x + threadIdx.x;
    if (e < E) {
        int r = edge_row(ei32, E, e);
        atomicAdd(&g_dinv[r], w[e]);
        atomicAdd(&g_cnt[r], 1);
    }
}

__global__ void dinv_kernel(int n) {
    int i = blockIdx.x * blockDim.x + threadIdx.x;
    if (i < n) {
        float d = g_dinv[i];
        g_dinv[i] = d > 0.0f ? rsqrtf(d) : 0.0f;
    }
}

__global__ void scan_block_kernel(int n) {
    __shared__ int sh[1024];
    int i = blockIdx.x * 1024 + threadIdx.x;
    int v = (i < n) ? g_cnt[i] : 0;
    sh[threadIdx.x] = v;
    __syncthreads();
    for (int off = 1; off < 1024; off <<= 1) {
        int t = (threadIdx.x >= off) ? sh[threadIdx.x - off] : 0;
        __syncthreads();
        sh[threadIdx.x] += t;
        __syncthreads();
    }
    if (i < n) g_rowptr[i] = sh[threadIdx.x] - v;
    if (threadIdx.x == 1023) g_bsum[blockIdx.x] = sh[1023];
}

__global__ void scan_bsum_kernel(int nb) {
    if (threadIdx.x == 0) {
        int acc = 0;
        for (int b = 0; b < nb; b++) { int t = g_bsum[b]; g_boff[b] = acc; acc += t; }
    }
}

__global__ void scan_add_kernel(int n, int E) {
    int i = blockIdx.x * 1024 + threadIdx.x;
    if (i < n) g_rowptr[i] += g_boff[i >> 10];
    if (i == n) g_rowptr[n] = E;
}

__global__ void fill_kernel(const int* __restrict__ ei32,
                            const float* __restrict__ w, int E) {
    int e = blockIdx.x * blockDim.x + threadIdx.x;
    if (e < E) {
        int r = edge_row(ei32, E, e);
        int c = edge_col(ei32, E, e);
        float nm = g_dinv[r] * w[e] * g_dinv[c];
        int idx = g_rowptr[r] + atomicAdd(&g_fill[r], 1);
        g_ccol[idx]  = c;
        g_cnorm[idx] = nm;
    }
}

// ---------------- HMMA GEMM (bf16 split x3): g_h = act(src) @ W ----------
// Block tile 128x128, 8 warps (4Mx2N), warp tile 32x64, BK=64, 2 chunks.
// smem rows padded to 72 bf16 (144 B, 16B-mult, conflict-free LDSM).
#define SROW 72
#define S_AHI 0
#define S_ALO 18432
#define S_BHI 36864
#define S_BLO 55296
#define S_TOTAL 73728

template <bool SRC_GA>
__global__ __launch_bounds__(256) void gemm_mma_kernel(
    const float* __restrict__ Aext,
    const uint* __restrict__ wthi, const uint* __restrict__ wtlo, int n)
{
    extern __shared__ char smem[];
    const uint32_t sb = smem_u32(smem);
    const int tid  = threadIdx.x;
    const int lane = tid & 31;
    const int wid  = tid >> 5;
    const int wm   = (wid & 3) * 32;     // warp M offset in tile
    const int wn   = (wid >> 2) * 64;    // warp N offset
    const int bm   = blockIdx.x * 128;
    const float* const src = SRC_GA ? g_a : Aext;

    const int lrow = lane & 15;
    const int lkof = (lane >> 4) << 3;   // 0 or 8

    float acc[2][8][4];
#pragma unroll
    for (int mi = 0; mi < 2; mi++)
#pragma unroll
        for (int nj = 0; nj < 8; nj++)
#pragma unroll
            for (int q = 0; q < 4; q++) acc[mi][nj][q] = 0.0f;

    for (int ch = 0; ch < 2; ch++) {
        // ---- stage A chunk [128 x 64] fp32 -> bf16 hi/lo smem ----
        {
            int row = tid >> 1;
            int kh  = (tid & 1) * 32;          // k-half within chunk
            int gr  = bm + row;
            const float* sp = src + (size_t)gr * FD + ch * 64 + kh;
            char* dh = smem + S_AHI + row * 144 + 2 * kh;
            char* dl = smem + S_ALO + row * 144 + 2 * kh;
#pragma unroll
            for (int j = 0; j < 8; j++) {
                float4 v = make_float4(0.f, 0.f, 0.f, 0.f);
                if (gr < n) {
                    v = *reinterpret_cast<const float4*>(sp + j * 4);
                    if (SRC_GA) {
                        v.x = fmaxf(v.x, 0.f); v.y = fmaxf(v.y, 0.f);
                        v.z = fmaxf(v.z, 0.f); v.w = fmaxf(v.w, 0.f);
                    }
                }
                unsigned short h0, l0, h1, l1, h2, l2, h3, l3;
                split_bf16(v.x, h0, l0); split_bf16(v.y, h1, l1);
                split_bf16(v.z, h2, l2); split_bf16(v.w, h3, l3);
                uint2 ph = make_uint2(((uint)h1 << 16) | h0, ((uint)h3 << 16) | h2);
                uint2 pl = make_uint2(((uint)l1 << 16) | l0, ((uint)l3 << 16) | l2);
                *reinterpret_cast<uint2*>(dh + j * 8) = ph;
                *reinterpret_cast<uint2*>(dl + j * 8) = pl;
            }
        }
        // ---- stage B chunk: Wt hi/lo [128 n x 64 k] bf16 ----
        {
            int row  = tid >> 1;
            int half = (tid & 1) * 16;         // 16 uints = 32 bf16
            const uint4* shp = reinterpret_cast<const uint4*>(wthi + row * 64 + ch * 32 + half);
            const uint4* slp = reinterpret_cast<const uint4*>(wtlo + row * 64 + ch * 32 + half);
            char* dh = smem + S_BHI + row * 144 + half * 4;
            char* dl = smem + S_BLO + row * 144 + half * 4;
#pragma unroll
            for (int j = 0; j < 4; j++) {
                *reinterpret_cast<uint4*>(dh + j * 16) = shp[j];
                *reinterpret_cast<uint4*>(dl + j * 16) = slp[j];
            }
        }
        __syncthreads();

        // ---- 4 k-steps of 16 ----
#pragma unroll
        for (int ks = 0; ks < 4; ks++) {
            int kk = ks * 16;
            uint ahi[2][4], alo[2][4], bfr[4][4];
#pragma unroll
            for (int mi = 0; mi < 2; mi++) {
                uint32_t off = (uint32_t)((wm + mi * 16 + lrow) * 144 + (kk + lkof) * 2);
                ldsm_x4(ahi[mi], sb + S_AHI + off);
                ldsm_x4(alo[mi], sb + S_ALO + off);
            }
            // product 1+2: (Ahi,Bhi) and (Alo,Bhi)
#pragma unroll
            for (int g = 0; g < 4; g++) {
                uint32_t off = (uint32_t)((wn + g * 16 + lrow) * 144 + (kk + lkof) * 2);
                ldsm_x4(bfr[g], sb + S_BHI + off);
            }
#pragma unroll
            for (int mi = 0; mi < 2; mi++)
#pragma unroll
                for (int g = 0; g < 4; g++) {
                    mma_bf16(acc[mi][2 * g + 0], ahi[mi], bfr[g][0], bfr[g][2]);
                    mma_bf16(acc[mi][2 * g + 1], ahi[mi], bfr[g][1], bfr[g][3]);
                    mma_bf16(acc[mi][2 * g + 0], alo[mi], bfr[g][0], bfr[g][2]);
                    mma_bf16(acc[mi][2 * g + 1], alo[mi], bfr[g][1], bfr[g][3]);
                }
            // product 3: (Ahi,Blo)
#pragma unroll
            for (int g = 0; g < 4; g++) {
                uint32_t off = (uint32_t)((wn + g * 16 + lrow) * 144 + (kk + lkof) * 2);
                ldsm_x4(bfr[g], sb + S_BLO + off);
            }
#pragma unroll
            for (int mi = 0; mi < 2; mi++)
#pragma unroll
                for (int g = 0; g < 4; g++) {
                    mma_bf16(acc[mi][2 * g + 0], ahi[mi], bfr[g][0], bfr[g][2]);
                    mma_bf16(acc[mi][2 * g + 1], ahi[mi], bfr[g][1], bfr[g][3]);
                }
        }
        __syncthreads();
    }

    // ---- epilogue: C fragments -> g_h ----
    const int crow = lane >> 2;
    const int ccol = (lane & 3) * 2;
#pragma unroll
    for (int mi = 0; mi < 2; mi++) {
        int r0 = bm + wm + mi * 16 + crow;
#pragma unroll
        for (int nj = 0; nj < 8; nj++) {
            int cc = wn + nj * 8 + ccol;
            if (r0 < n)
                *reinterpret_cast<float2*>(g_h + (size_t)r0 * FD + cc) =
                    make_float2(acc[mi][nj][0], acc[mi][nj][1]);
            if (r0 + 8 < n)
                *reinterpret_cast<float2*>(g_h + (size_t)(r0 + 8) * FD + cc) =
                    make_float2(acc[mi][nj][2], acc[mi][nj][3]);
        }
    }
}

// ---------------- CSR aggregation: one warp per node ----------------
template <bool DST_GA>
__global__ void agg_csr_kernel(const float* __restrict__ bias,
                               float* __restrict__ outExt, int n)
{
    int r    = (blockIdx.x * blockDim.x + threadIdx.x) >> 5;
    int lane = threadIdx.x & 31;
    if (r >= n) return;
    int f4 = lane << 2;

    float di = g_dinv[r];
    float s  = di * di;
    float4 hv = *reinterpret_cast<const float4*>(g_h + (size_t)r * FD + f4);
    float4 bv = *reinterpret_cast<const float4*>(bias + f4);
    float4 acc = make_float4(fmaf(s, hv.x, bv.x), fmaf(s, hv.y, bv.y),
                             fmaf(s, hv.z, bv.z), fmaf(s, hv.w, bv.w));

    int e   = g_rowptr[r];
    int end = g_rowptr[r + 1];
    for (; e + 2 <= end; e += 2) {
        int   c0 = g_ccol[e],  c1 = g_ccol[e + 1];
        float n0 = g_cnorm[e], n1 = g_cnorm[e + 1];
        float4 h0 = *reinterpret_cast<const float4*>(g_h + (size_t)c0 * FD + f4);
        float4 h1 = *reinterpret_cast<const float4*>(g_h + (size_t)c1 * FD + f4);
        acc.x = fmaf(n0, h0.x, acc.x); acc.y = fmaf(n0, h0.y, acc.y);
        acc.z = fmaf(n0, h0.z, acc.z); acc.w = fmaf(n0, h0.w, acc.w);
        acc.x = fmaf(n1, h1.x, acc.x); acc.y = fmaf(n1, h1.y, acc.y);
        acc.z = fmaf(n1, h1.z, acc.z); acc.w = fmaf(n1, h1.w, acc.w);
    }
    if (e < end) {
        int   c0 = g_ccol[e];
        float n0 = g_cnorm[e];
        float4 h0 = *reinterpret_cast<const float4*>(g_h + (size_t)c0 * FD + f4);
        acc.x = fmaf(n0, h0.x, acc.x); acc.y = fmaf(n0, h0.y, acc.y);
        acc.z = fmaf(n0, h0.z, acc.z); acc.w = fmaf(n0, h0.w, acc.w);
    }

    float* dst = DST_GA ? g_a : outExt;
    *reinterpret_cast<float4*>(dst + (size_t)r * FD + f4) = acc;
}

// ---------------- launch ----------------
extern "C" void kernel_launch(void* const* d_in, const int* in_sizes, int n_in,
                              void* d_out, int out_size)
{
    const float* x    = (const float*)d_in[0];
    const int*   ei32 = (const int*)d_in[1];
    const float* ew   = (const float*)d_in[2];
    const float* W1   = (const float*)d_in[3];
    const float* b1   = (const float*)d_in[4];
    const float* W2   = (const float*)d_in[5];
    const float* b2   = (const float*)d_in[6];
    float* out = (float*)d_out;

    const int n = in_sizes[0] / FD;
    const int E = in_sizes[2];

    cudaFuncSetAttribute(gemm_mma_kernel<false>,
                         cudaFuncAttributeMaxDynamicSharedMemorySize, S_TOTAL);
    cudaFuncSetAttribute(gemm_mma_kernel<true>,
                         cudaFuncAttributeMaxDynamicSharedMemorySize, S_TOTAL);

    const int gemm_blocks = (n + 127) / 128;
    const int agg_blocks  = (n * 32 + 255) / 256;
    const int scan_blocks = (n + 1023) / 1024;

    zero_detect_kernel<<<(n + 255) / 256, 256>>>(ei32, E, n);             // 0
    wconv_kernel<<<32, 256>>>(W1, g_wthi1, g_wtlo1);                      // 1
    wconv_kernel<<<32, 256>>>(W2, g_wthi2, g_wtlo2);                      // 2
    gemm_mma_kernel<false><<<gemm_blocks, 256, S_TOTAL>>>(x, g_wthi1, g_wtlo1, n); // 3 <- profiled
    deg_count_kernel<<<(E + 255) / 256, 256>>>(ei32, ew, E);              // 4
    dinv_kernel<<<(n + 255) / 256, 256>>>(n);                             // 5
    scan_block_kernel<<<scan_blocks, 1024>>>(n);                          // 6
    scan_bsum_kernel<<<1, 32>>>(scan_blocks);                             // 7
    scan_add_kernel<<<(n + 1024) / 1024, 1024>>>(n, E);                   // 8
    fill_kernel<<<(E + 255) / 256, 256>>>(ei32, ew, E);                   // 9
    agg_csr_kernel<true><<<agg_blocks, 256>>>(b1, nullptr, n);            // 10
    gemm_mma_kernel<true><<<gemm_blocks, 256, S_TOTAL>>>(nullptr, g_wthi2, g_wtlo2, n); // 11
    agg_csr_kernel<false><<<agg_blocks, 256>>>(b2, out, n);               // 12
}

// round 11
// speedup vs baseline: 2.7441x; 2.7441x over previous
#include <cuda_runtime.h>
#include <cstdint>
#include <cstddef>

#define NMAX 100000
#define EMAX 1700000
#define FD 128

typedef unsigned long long ull;
typedef unsigned int uint;

// Scratch — static __device__ globals, referenced only from device code.
__device__ __align__(16) float g_dinv[NMAX];
__device__ __align__(16) float g_h[(size_t)NMAX * FD];   // GEMM output
__device__ __align__(16) float g_a[(size_t)NMAX * FD];   // layer-1 activation
__device__ int   g_is64;
// CSR
__device__ int   g_cnt[NMAX];
__device__ int   g_fill[NMAX];
__device__ int   g_rowptr[NMAX + 1];
__device__ int   g_bsum[128];
__device__ int   g_boff[128];
__device__ int   g_ccol[EMAX];
__device__ float g_cnorm[EMAX];

// ---------------- packed fp32x2 FMA (sm_103a FFMA2) ----------------
__device__ __forceinline__ ull ffma2(ull a, ull b, ull c) {
    ull d;
    asm("fma.rn.f32x2 %0, %1, %2, %3;" : "=l"(d) : "l"(a), "l"(b), "l"(c));
    return d;
}
__device__ __forceinline__ ull dup_f32(float a) {
    ull d;
    asm("mov.b64 %0, {%1, %2};" : "=l"(d) : "f"(a), "f"(a));
    return d;
}
__device__ __forceinline__ float2 unpack_f32x2(ull v) {
    float2 r;
    asm("mov.b64 {%0, %1}, %2;" : "=f"(r.x), "=f"(r.y) : "l"(v));
    return r;
}

// B smem anti-conflict mapping: byte = c*4 + (c>>5)*16, row stride 576 B.
__device__ __forceinline__ int bcol_byte(int c) { return c * 4 + ((c >> 5) << 4); }

// ---------------- zero + dtype detection ----------------
__global__ void zero_detect_kernel(const int* __restrict__ ei32, int E, int n) {
    int i = blockIdx.x * blockDim.x + threadIdx.x;
    if (i < n) { g_dinv[i] = 1.0f; g_cnt[i] = 0; g_fill[i] = 0; }
    if (blockIdx.x == 0) {
        __shared__ int snz;
        if (threadIdx.x == 0) snz = 0;
        __syncthreads();
        int cnt = E < 4096 ? E : 4096, nz = 0;
        for (int j = threadIdx.x; j < cnt; j += blockDim.x) nz |= ei32[2 * j + 1];
        if (nz) atomicOr(&snz, 1);
        __syncthreads();
        if (threadIdx.x == 0) g_is64 = (snz == 0) ? 1 : 0;
    }
}

__device__ __forceinline__ int edge_row(const int* ei32, int E, int e) {
    return g_is64 ? ei32[2 * (size_t)e] : ei32[e];
}
__device__ __forceinline__ int edge_col(const int* ei32, int E, int e) {
    return g_is64 ? ei32[2 * (size_t)E + 2 * (size_t)e] : ei32[(size_t)E + e];
}

// ---------------- degree + CSR build ----------------
__global__ void deg_count_kernel(const int* __restrict__ ei32,
                                 const float* __restrict__ w, int E) {
    int e = blockIdx.x * blockDim.x + threadIdx.x;
    if (e < E) {
        int r = edge_row(ei32, E, e);
        atomicAdd(&g_dinv[r], w[e]);
        atomicAdd(&g_cnt[r], 1);
    }
}

__global__ void dinv_kernel(int n) {
    int i = blockIdx.x * blockDim.x + threadIdx.x;
    if (i < n) {
        float d = g_dinv[i];
        g_dinv[i] = d > 0.0f ? rsqrtf(d) : 0.0f;
    }
}

__global__ void scan_block_kernel(int n) {
    __shared__ int sh[1024];
    int i = blockIdx.x * 1024 + threadIdx.x;
    int v = (i < n) ? g_cnt[i] : 0;
    sh[threadIdx.x] = v;
    __syncthreads();
    for (int off = 1; off < 1024; off <<= 1) {
        int t = (threadIdx.x >= off) ? sh[threadIdx.x - off] : 0;
        __syncthreads();
        sh[threadIdx.x] += t;
        __syncthreads();
    }
    if (i < n) g_rowptr[i] = sh[threadIdx.x] - v;
    if (threadIdx.x == 1023) g_bsum[blockIdx.x] = sh[1023];
}

__global__ void scan_bsum_kernel(int nb) {
    if (threadIdx.x == 0) {
        int acc = 0;
        for (int b = 0; b < nb; b++) { int t = g_bsum[b]; g_boff[b] = acc; acc += t; }
    }
}

__global__ void scan_add_kernel(int n, int E) {
    int i = blockIdx.x * 1024 + threadIdx.x;
    if (i < n) g_rowptr[i] += g_boff[i >> 10];
    if (i == n) g_rowptr[n] = E;
}

__global__ void fill_kernel(const int* __restrict__ ei32,
                            const float* __restrict__ w, int E) {
    int e = blockIdx.x * blockDim.x + threadIdx.x;
    if (e < E) {
        int r = edge_row(ei32, E, e);
        int c = edge_col(ei32, E, e);
        float nm = g_dinv[r] * w[e] * g_dinv[c];
        int idx = g_rowptr[r] + atomicAdd(&g_fill[r], 1);
        g_ccol[idx]  = c;
        g_cnorm[idx] = nm;
    }
}

// ---------------- SGEMM (FFMA2, 2 CTAs/SM, conflict-free B) -------------
// As: transposed [k][m], 132-float rows. Ws: [k] x 576-byte padded rows.

__global__ __launch_bounds__(256, 2) void sgemm_kernel_t(
    const float* __restrict__ Aext, const float* __restrict__ W, int n, int relu_in)
{
    __shared__ float As[32][132];
    __shared__ __align__(16) char WsB[32 * 576];

    const int bm  = blockIdx.x * 128;
    const int tid = threadIdx.x;
    const int tm  = (tid >> 4) << 3;
    const int tn  = (tid & 15) << 3;
    const float* const src = Aext;

    ull acc2[8][4];
#pragma unroll
    for (int i = 0; i < 8; i++)
#pragma unroll
        for (int j = 0; j < 4; j++) acc2[i][j] = 0ull;

    // mainloop B read addresses (conflict-free padded layout)
    char* const wrow0 = WsB + bcol_byte(tn);
    char* const wrow1 = WsB + bcol_byte(tn + 4);

    for (int k0 = 0; k0 < 128; k0 += 32) {
        // stage A tile 128x32 (transposed)
#pragma unroll
        for (int i = 0; i < 4; i++) {
            int t  = tid + i * 256;
            int r  = t >> 3;
            int c4 = (t & 7) << 2;
            int gr = bm + r;
            float4 v = make_float4(0.f, 0.f, 0.f, 0.f);
            if (gr < n) {
                v = *reinterpret_cast<const float4*>(src + (size_t)gr * FD + k0 + c4);
                if (relu_in) {
                    v.x = fmaxf(v.x, 0.f); v.y = fmaxf(v.y, 0.f);
                    v.z = fmaxf(v.z, 0.f); v.w = fmaxf(v.w, 0.f);
                }
            }
            As[c4 + 0][r] = v.x; As[c4 + 1][r] = v.y;
            As[c4 + 2][r] = v.z; As[c4 + 3][r] = v.w;
        }
        // stage W tile 32x128 into padded layout
#pragma unroll
        for (int i = 0; i < 4; i++) {
            int t  = tid + i * 256;
            int r  = t >> 5;
            int c4 = (t & 31) << 2;
            float4 v = *reinterpret_cast<const float4*>(W + (size_t)(k0 + r) * FD + c4);
            *reinterpret_cast<float4*>(WsB + r * 576 + bcol_byte(c4)) = v;
        }
        __syncthreads();

#pragma unroll
        for (int k = 0; k < 32; k++) {
            float a[8];
            *reinterpret_cast<float4*>(a)     = *reinterpret_cast<float4*>(&As[k][tm]);
            *reinterpret_cast<float4*>(a + 4) = *reinterpret_cast<float4*>(&As[k][tm + 4]);
            ulonglong2 bq0 = *reinterpret_cast<ulonglong2*>(wrow0 + k * 576);
            ulonglong2 bq1 = *reinterpret_cast<ulonglong2*>(wrow1 + k * 576);
            ull b2[4] = {bq0.x, bq0.y, bq1.x, bq1.y};
            ull ad[8];
#pragma unroll
            for (int i = 0; i < 8; i++) ad[i] = dup_f32(a[i]);
#pragma unroll
            for (int i = 0; i < 8; i++)
#pragma unroll
                for (int j = 0; j < 4; j++)
                    acc2[i][j] = ffma2(ad[i], b2[j], acc2[i][j]);
        }
        __syncthreads();
    }

#pragma unroll
    for (int i = 0; i < 8; i++) {
        int gr = bm + tm + i;
        if (gr < n) {
            float2 p0 = unpack_f32x2(acc2[i][0]);
            float2 p1 = unpack_f32x2(acc2[i][1]);
            float2 p2 = unpack_f32x2(acc2[i][2]);
            float2 p3 = unpack_f32x2(acc2[i][3]);
            *reinterpret_cast<float4*>(g_h + (size_t)gr * FD + tn) =
                make_float4(p0.x, p0.y, p1.x, p1.y);
            *reinterpret_cast<float4*>(g_h + (size_t)gr * FD + tn + 4) =
                make_float4(p2.x, p2.y, p3.x, p3.y);
        }
    }
}

// wrapper picking src = external x (layer 1) or g_a with relu (layer 2)
__global__ __launch_bounds__(256, 2) void sgemm_kernel_ga(
    const float* __restrict__ W, int n);

// (separate definition to keep pointer-to-global indirection out of hot loop)
__global__ __launch_bounds__(256, 2) void sgemm_kernel_ga(
    const float* __restrict__ W, int n)
{
    __shared__ float As[32][132];
    __shared__ __align__(16) char WsB[32 * 576];

    const int bm  = blockIdx.x * 128;
    const int tid = threadIdx.x;
    const int tm  = (tid >> 4) << 3;
    const int tn  = (tid & 15) << 3;

    ull acc2[8][4];
#pragma unroll
    for (int i = 0; i < 8; i++)
#pragma unroll
        for (int j = 0; j < 4; j++) acc2[i][j] = 0ull;

    char* const wrow0 = WsB + bcol_byte(tn);
    char* const wrow1 = WsB + bcol_byte(tn + 4);

    for (int k0 = 0; k0 < 128; k0 += 32) {
#pragma unroll
        for (int i = 0; i < 4; i++) {
            int t  = tid + i * 256;
            int r  = t >> 3;
            int c4 = (t & 7) << 2;
            int gr = bm + r;
            float4 v = make_float4(0.f, 0.f, 0.f, 0.f);
            if (gr < n) {
                v = *reinterpret_cast<const float4*>(g_a + (size_t)gr * FD + k0 + c4);
                v.x = fmaxf(v.x, 0.f); v.y = fmaxf(v.y, 0.f);
                v.z = fmaxf(v.z, 0.f); v.w = fmaxf(v.w, 0.f);
            }
            As[c4 + 0][r] = v.x; As[c4 + 1][r] = v.y;
            As[c4 + 2][r] = v.z; As[c4 + 3][r] = v.w;
        }
#pragma unroll
        for (int i = 0; i < 4; i++) {
            int t  = tid + i * 256;
            int r  = t >> 5;
            int c4 = (t & 31) << 2;
            float4 v = *reinterpret_cast<const float4*>(W + (size_t)(k0 + r) * FD + c4);
            *reinterpret_cast<float4*>(WsB + r * 576 + bcol_byte(c4)) = v;
        }
        __syncthreads();

#pragma unroll
        for (int k = 0; k < 32; k++) {
            float a[8];
            *reinterpret_cast<float4*>(a)     = *reinterpret_cast<float4*>(&As[k][tm]);
            *reinterpret_cast<float4*>(a + 4) = *reinterpret_cast<float4*>(&As[k][tm + 4]);
            ulonglong2 bq0 = *reinterpret_cast<ulonglong2*>(wrow0 + k * 576);
            ulonglong2 bq1 = *reinterpret_cast<ulonglong2*>(wrow1 + k * 576);
            ull b2[4] = {bq0.x, bq0.y, bq1.x, bq1.y};
            ull ad[8];
#pragma unroll
            for (int i = 0; i < 8; i++) ad[i] = dup_f32(a[i]);
#pragma unroll
            for (int i = 0; i < 8; i++)
#pragma unroll
                for (int j = 0; j < 4; j++)
                    acc2[i][j] = ffma2(ad[i], b2[j], acc2[i][j]);
        }
        __syncthreads();
    }

#pragma unroll
    for (int i = 0; i < 8; i++) {
        int gr = bm + tm + i;
        if (gr < n) {
            float2 p0 = unpack_f32x2(acc2[i][0]);
            float2 p1 = unpack_f32x2(acc2[i][1]);
            float2 p2 = unpack_f32x2(acc2[i][2]);
            float2 p3 = unpack_f32x2(acc2[i][3]);
            *reinterpret_cast<float4*>(g_h + (size_t)gr * FD + tn) =
                make_float4(p0.x, p0.y, p1.x, p1.y);
            *reinterpret_cast<float4*>(g_h + (size_t)gr * FD + tn + 4) =
                make_float4(p2.x, p2.y, p3.x, p3.y);
        }
    }
}

// ---------------- CSR aggregation: one warp per node ----------------
template <bool DST_GA>
__global__ void agg_csr_kernel(const float* __restrict__ bias,
                               float* __restrict__ outExt, int n)
{
    int r    = (blockIdx.x * blockDim.x + threadIdx.x) >> 5;
    int lane = threadIdx.x & 31;
    if (r >= n) return;
    int f4 = lane << 2;

    float di = g_dinv[r];
    float s  = di * di;
    float4 hv = *reinterpret_cast<const float4*>(g_h + (size_t)r * FD + f4);
    float4 bv = *reinterpret_cast<const float4*>(bias + f4);
    float4 acc = make_float4(fmaf(s, hv.x, bv.x), fmaf(s, hv.y, bv.y),
                             fmaf(s, hv.z, bv.z), fmaf(s, hv.w, bv.w));

    int e   = g_rowptr[r];
    int end = g_rowptr[r + 1];
    for (; e + 2 <= end; e += 2) {
        int   c0 = g_ccol[e],  c1 = g_ccol[e + 1];
        float n0 = g_cnorm[e], n1 = g_cnorm[e + 1];
        float4 h0 = *reinterpret_cast<const float4*>(g_h + (size_t)c0 * FD + f4);
        float4 h1 = *reinterpret_cast<const float4*>(g_h + (size_t)c1 * FD + f4);
        acc.x = fmaf(n0, h0.x, acc.x); acc.y = fmaf(n0, h0.y, acc.y);
        acc.z = fmaf(n0, h0.z, acc.z); acc.w = fmaf(n0, h0.w, acc.w);
        acc.x = fmaf(n1, h1.x, acc.x); acc.y = fmaf(n1, h1.y, acc.y);
        acc.z = fmaf(n1, h1.z, acc.z); acc.w = fmaf(n1, h1.w, acc.w);
    }
    if (e < end) {
        int   c0 = g_ccol[e];
        float n0 = g_cnorm[e];
        float4 h0 = *reinterpret_cast<const float4*>(g_h + (size_t)c0 * FD + f4);
        acc.x = fmaf(n0, h0.x, acc.x); acc.y = fmaf(n0, h0.y, acc.y);
        acc.z = fmaf(n0, h0.z, acc.z); acc.w = fmaf(n0, h0.w, acc.w);
    }

    float* dst = DST_GA ? g_a : outExt;
    *reinterpret_cast<float4*>(dst + (size_t)r * FD + f4) = acc;
}

// ---------------- launch ----------------
extern "C" void kernel_launch(void* const* d_in, const int* in_sizes, int n_in,
                              void* d_out, int out_size)
{
    const float* x    = (const float*)d_in[0];
    const int*   ei32 = (const int*)d_in[1];
    const float* ew   = (const float*)d_in[2];
    const float* W1   = (const float*)d_in[3];
    const float* b1   = (const float*)d_in[4];
    const float* W2   = (const float*)d_in[5];
    const float* b2   = (const float*)d_in[6];
    float* out = (float*)d_out;

    const int n = in_sizes[0] / FD;
    const int E = in_sizes[2];

    const int gemm_blocks = (n + 127) / 128;
    const int agg_blocks  = (n * 32 + 255) / 256;
    const int scan_blocks = (n + 1023) / 1024;

    zero_detect_kernel<<<(n + 255) / 256, 256>>>(ei32, E, n);       // 0
    deg_count_kernel<<<(E + 255) / 256, 256>>>(ei32, ew, E);        // 1
    dinv_kernel<<<(n + 255) / 256, 256>>>(n);                       // 2
    sgemm_kernel_t<<<gemm_blocks, 256>>>(x, W1, n, 0);              // 3 <- profiled
    scan_block_kernel<<<scan_blocks, 1024>>>(n);                    // 4
    scan_bsum_kernel<<<1, 32>>>(scan_blocks);                       // 5
    scan_add_kernel<<<(n + 1024) / 1024, 1024>>>(n, E);             // 6
    fill_kernel<<<(E + 255) / 256, 256>>>(ei32, ew, E);             // 7
    agg_csr_kernel<true><<<agg_blocks, 256>>>(b1, nullptr, n);      // 8
    sgemm_kernel_ga<<<gemm_blocks, 256>>>(W2, n);                   // 9
    agg_csr_kernel<false><<<agg_blocks, 256>>>(b2, out, n);         // 10
}